// round 9
// baseline (speedup 1.0000x reference)
#include <cuda_runtime.h>
#include <cuda_bf16.h>

// Problem constants (fixed by the reference)
#define PB 64
#define PT 512
#define PD 1024
#define TT 8                   // rows per contributor chunk (small => HW backfill)
#define TS (PT / TT)           // 64 t-chunks
#define NCONTRIB (2 * TS)      // 128 contributor blocks per b

// Zero-invariant scratch: statically zero-initialized at module load; the
// per-b finalizer restores zeros after consuming, so every kernel_launch call
// (correctness run + each graph replay) sees zeros.
__device__ float    g_S  [PB * PD];  // unnormalized s[b,d]
__device__ float    g_YH [PB * PD];  // unnormalized y_hat[b,d]
__device__ unsigned g_cnt[PB];       // per-b arrival counters

// One vectorized no-return reduction: 1 LTS op per float4 (sm_90+).
__device__ __forceinline__ void red_add_v4(float* p, float4 v)
{
    asm volatile("red.global.add.v4.f32 [%0], {%1, %2, %3, %4};"
                 :: "l"(p), "f"(v.x), "f"(v.y), "f"(v.z), "f"(v.w) : "memory");
}

// ---------------------------------------------------------------------------
// Single fused kernel. grid (2, TS+1, PB), block 128.
//   by <  TS : contributor — CONTIGUOUS 8-row t-chunk [8*by, 8*by+8) ∩ [0,L).
//              Fully-masked chunks exit before any global load; with ~56
//              blocks/SM queued, the HW scheduler backfills retired slots,
//              giving dynamic load balance without changing the (proven)
//              contiguous access pattern. Partial sums -> red.v4 into
//              g_S/g_YH, then ONE release-increment of g_cnt[b] by thread 0.
//   by == TS, bx == 0 : finalizer for b — acquire-spin until all 128
//              contributors arrived, then L1-norm + outputs + scratch reset.
// ---------------------------------------------------------------------------
__global__ void __launch_bounds__(128)
k_fused(const float* __restrict__ vs,
        const int*   __restrict__ len,
        const int*   __restrict__ word,
        const float* __restrict__ weights,
        float*       __restrict__ out)
{
    const int b = blockIdx.z;

    if (blockIdx.y == TS) {
        if (blockIdx.x != 0) return;
        // ---------------- finalizer for batch b ----------------
        unsigned* cnt = &g_cnt[b];
        if (threadIdx.x == 0) {
            unsigned v;
            for (;;) {
                asm volatile("ld.acquire.gpu.global.u32 %0, [%1];"
                             : "=r"(v) : "l"(cnt) : "memory");
                if (v >= NCONTRIB) break;
                __nanosleep(64);
            }
            *cnt = 0;  // reset for next replay (kernel-boundary ordering)
        }
        __syncthreads();

        const int tid = threadIdx.x;
        float4* sB = reinterpret_cast<float4*>(g_S  + (size_t)b * PD);
        float4* hB = reinterpret_cast<float4*>(g_YH + (size_t)b * PD);

        float4 s[2], h[2];
#pragma unroll
        for (int j = 0; j < 2; ++j) {
            s[j] = __ldcg(sB + tid + 128 * j);
            h[j] = __ldcg(hB + tid + 128 * j);
        }

        float part = 0.f;
#pragma unroll
        for (int j = 0; j < 2; ++j)
            part += fabsf(s[j].x) + fabsf(s[j].y) + fabsf(s[j].z) + fabsf(s[j].w);

#pragma unroll
        for (int o = 16; o > 0; o >>= 1)
            part += __shfl_xor_sync(0xFFFFFFFFu, part, o);

        __shared__ float sm[4];
        if ((tid & 31) == 0) sm[tid >> 5] = part;
        __syncthreads();
        float tot = sm[0] + sm[1] + sm[2] + sm[3];

        const float r = rsqrtf(tot);

        float4* outY = reinterpret_cast<float4*>(out + (size_t)b * PD);
        float4* outH = reinterpret_cast<float4*>(out + (size_t)(PB + b) * PD);
        const float4 z = make_float4(0.f, 0.f, 0.f, 0.f);
#pragma unroll
        for (int j = 0; j < 2; ++j) {
            outY[tid + 128 * j] =
                make_float4(s[j].x * r, s[j].y * r, s[j].z * r, s[j].w * r);
            outH[tid + 128 * j] = h[j];
            sB[tid + 128 * j] = z;   // restore zero-invariant
            hB[tid + 128 * j] = z;
        }
        return;
    }

    // ---------------- contributor ----------------
    const int L  = __ldg(len + b);
    const int t0 = blockIdx.y * TT;

    if (t0 < L) {
        const int n = min(L - t0, TT);

        // Warp gather: lane j (j<8) holds weights[word[b, t0+j]]; lanes 8+
        // duplicate lane j&7 (keeps indices in-bounds). Broadcast via shfl.
        const int   lane  = threadIdx.x & 31;
        const float wlane = weights[word[b * PT + t0 + (lane & (TT - 1))]];

        const int d0 = blockIdx.x * 512 + threadIdx.x * 4;

        const float4* __restrict__ p =
            reinterpret_cast<const float4*>(vs + ((size_t)b * PT + t0) * PD + d0);
        const size_t stride = PD / 4;           // next row: 4KB away

        float4 acc  = make_float4(0.f, 0.f, 0.f, 0.f);
        float4 accw = make_float4(0.f, 0.f, 0.f, 0.f);

#pragma unroll
        for (int i = 0; i < TT; ++i) {
            if (i >= n) break;
            const float4 v = p[(size_t)i * stride];
            const float  w = __shfl_sync(0xFFFFFFFFu, wlane, i);
            acc.x  += v.x;      acc.y  += v.y;      acc.z  += v.z;      acc.w  += v.w;
            accw.x += w * v.x;  accw.y += w * v.y;  accw.z += w * v.z;  accw.w += w * v.w;
        }

        red_add_v4(g_S  + (size_t)b * PD + d0, acc);
        red_add_v4(g_YH + (size_t)b * PD + d0, accw);
    }

    // Arrival: CTA barrier (happens-before from all threads to thread 0),
    // then a single gpu-scope release increment. Cumulativity makes every
    // thread's reductions visible to the finalizer's acquire.
    __syncthreads();
    if (threadIdx.x == 0) {
        asm volatile("red.release.gpu.global.add.u32 [%0], %1;"
                     :: "l"(&g_cnt[b]), "r"(1u) : "memory");
    }
}

// ---------------------------------------------------------------------------
// Entry point: one kernel, one launch.
// ---------------------------------------------------------------------------
extern "C" void kernel_launch(void* const* d_in, const int* in_sizes, int n_in,
                              void* d_out, int out_size)
{
    const float* vs      = (const float*)d_in[0];  // [B,T,D] f32
    const int*   len     = (const int*)  d_in[1];  // [B]
    const int*   word    = (const int*)  d_in[2];  // [B,T]
    const float* weights = (const float*)d_in[3];  // [VOCAB]

    float* out = (float*)d_out;  // y at [0, B*D), y_hat at [B*D, 2*B*D)

    k_fused<<<dim3(2, TS + 1, PB), 128>>>(vs, len, word, weights, out);
}

// round 10
// speedup vs baseline: 1.5539x; 1.5539x over previous
#include <cuda_runtime.h>
#include <cuda_bf16.h>

// Problem constants (fixed by the reference)
#define PB 64
#define PT 512
#define PD 1024
#define TS 16                 // t-slices per b (per d-half)
#define NCONTRIB (2 * TS)     // 32 contributor blocks per b

// Zero-invariant scratch: statically zero-initialized at module load; the
// per-b finalizer restores zeros after consuming, so every kernel_launch call
// (correctness run + each graph replay) sees zeros.
__device__ float    g_S  [PB * PD];  // unnormalized s[b,d]
__device__ float    g_YH [PB * PD];  // unnormalized y_hat[b,d]
__device__ unsigned g_cnt[PB];       // per-b arrival counters

// One vectorized no-return reduction: 1 LTS op per float4 (sm_90+).
__device__ __forceinline__ void red_add_v4(float* p, float4 v)
{
    asm volatile("red.global.add.v4.f32 [%0], {%1, %2, %3, %4};"
                 :: "l"(p), "f"(v.x), "f"(v.y), "f"(v.z), "f"(v.w) : "memory");
}

// ---------------------------------------------------------------------------
// Single fused kernel. grid (2, TS+1, PB), block 128.
//   by <  TS : contributor — PROPORTIONAL CONTIGUOUS slice of [0,L):
//              rows [ceil(by*L/16), ceil((by+1)*L/16)), i.e. ~L/16 rows,
//              contiguous at 4KB row stride (the proven access pattern).
//              Work per block is smooth in L -> per-SM totals balance within
//              the single wave. Partials -> red.v4, then ONE release-inc of
//              g_cnt[b] by thread 0.
//   by == TS, bx == 0 : finalizer for b — acquire-spin until all 32
//              contributors arrived, then L1-norm + outputs + scratch reset.
// ---------------------------------------------------------------------------
__global__ void __launch_bounds__(128)
k_fused(const float* __restrict__ vs,
        const int*   __restrict__ len,
        const int*   __restrict__ word,
        const float* __restrict__ weights,
        float*       __restrict__ out)
{
    const int b = blockIdx.z;

    if (blockIdx.y == TS) {
        if (blockIdx.x != 0) return;
        // ---------------- finalizer for batch b ----------------
        unsigned* cnt = &g_cnt[b];
        if (threadIdx.x == 0) {
            unsigned v;
            for (;;) {
                asm volatile("ld.acquire.gpu.global.u32 %0, [%1];"
                             : "=r"(v) : "l"(cnt) : "memory");
                if (v >= NCONTRIB) break;
                __nanosleep(64);
            }
            *cnt = 0;  // reset for next replay (kernel-boundary ordering)
        }
        __syncthreads();

        const int tid = threadIdx.x;
        float4* sB = reinterpret_cast<float4*>(g_S  + (size_t)b * PD);
        float4* hB = reinterpret_cast<float4*>(g_YH + (size_t)b * PD);

        float4 s[2], h[2];
#pragma unroll
        for (int j = 0; j < 2; ++j) {
            s[j] = __ldcg(sB + tid + 128 * j);
            h[j] = __ldcg(hB + tid + 128 * j);
        }

        float part = 0.f;
#pragma unroll
        for (int j = 0; j < 2; ++j)
            part += fabsf(s[j].x) + fabsf(s[j].y) + fabsf(s[j].z) + fabsf(s[j].w);

#pragma unroll
        for (int o = 16; o > 0; o >>= 1)
            part += __shfl_xor_sync(0xFFFFFFFFu, part, o);

        __shared__ float sm[4];
        if ((tid & 31) == 0) sm[tid >> 5] = part;
        __syncthreads();
        float tot = sm[0] + sm[1] + sm[2] + sm[3];

        const float r = rsqrtf(tot);

        float4* outY = reinterpret_cast<float4*>(out + (size_t)b * PD);
        float4* outH = reinterpret_cast<float4*>(out + (size_t)(PB + b) * PD);
        const float4 z = make_float4(0.f, 0.f, 0.f, 0.f);
#pragma unroll
        for (int j = 0; j < 2; ++j) {
            outY[tid + 128 * j] =
                make_float4(s[j].x * r, s[j].y * r, s[j].z * r, s[j].w * r);
            outH[tid + 128 * j] = h[j];
            sB[tid + 128 * j] = z;   // restore zero-invariant
            hB[tid + 128 * j] = z;
        }
        return;
    }

    // ---------------- contributor ----------------
    const int L  = __ldg(len + b);
    const int by = blockIdx.y;
    const int lo = (by * L + TS - 1) >> 4;        // ceil(by*L/16)
    const int hi = ((by + 1) * L + TS - 1) >> 4;  // ceil((by+1)*L/16)
    const int n  = hi - lo;                       // 0..32 contiguous rows

    if (n > 0) {
        // Warp-wide weight gather: lane j holds weights[word[b, lo+j]] for
        // j < n; lanes >= n read a safe in-bounds index (value unused).
        const int   lane   = threadIdx.x & 31;
        const int   safe_t = lo + ((lane < n) ? lane : 0);
        const float wlane  = weights[word[b * PT + safe_t]];

        const int d0 = blockIdx.x * 512 + threadIdx.x * 4;

        const float4* __restrict__ p =
            reinterpret_cast<const float4*>(vs + ((size_t)b * PT + lo) * PD + d0);
        const size_t stride = PD / 4;             // next row: 4KB away

        float4 acc  = make_float4(0.f, 0.f, 0.f, 0.f);
        float4 accw = make_float4(0.f, 0.f, 0.f, 0.f);

#pragma unroll 4
        for (int i = 0; i < n; ++i) {
            const float4 v = p[(size_t)i * stride];
            const float  w = __shfl_sync(0xFFFFFFFFu, wlane, i);
            acc.x  += v.x;      acc.y  += v.y;      acc.z  += v.z;      acc.w  += v.w;
            accw.x += w * v.x;  accw.y += w * v.y;  accw.z += w * v.z;  accw.w += w * v.w;
        }

        red_add_v4(g_S  + (size_t)b * PD + d0, acc);
        red_add_v4(g_YH + (size_t)b * PD + d0, accw);
    }

    // Arrival: CTA barrier (happens-before from all threads to thread 0),
    // then a single gpu-scope release increment. Cumulativity makes every
    // thread's reductions visible to the finalizer's acquire.
    __syncthreads();
    if (threadIdx.x == 0) {
        asm volatile("red.release.gpu.global.add.u32 [%0], %1;"
                     :: "l"(&g_cnt[b]), "r"(1u) : "memory");
    }
}

// ---------------------------------------------------------------------------
// Entry point: one kernel, one launch.
// ---------------------------------------------------------------------------
extern "C" void kernel_launch(void* const* d_in, const int* in_sizes, int n_in,
                              void* d_out, int out_size)
{
    const float* vs      = (const float*)d_in[0];  // [B,T,D] f32
    const int*   len     = (const int*)  d_in[1];  // [B]
    const int*   word    = (const int*)  d_in[2];  // [B,T]
    const float* weights = (const float*)d_in[3];  // [VOCAB]

    float* out = (float*)d_out;  // y at [0, B*D), y_hat at [B*D, 2*B*D)

    k_fused<<<dim3(2, TS + 1, PB), 128>>>(vs, len, word, weights, out);
}